// round 1
// baseline (speedup 1.0000x reference)
#include <cuda_runtime.h>
#include <math.h>

#define EPSQ 1e-8f

// Pre-normalized codebook scratch (K=1024, D=256)
__device__ float g_cbs[1024 * 256];

// ---------- packed f32x2 helpers (sm_103a: 2x FFMA throughput vs 3-reg FFMA) ----------
__device__ __forceinline__ unsigned long long pack2(float x, float y) {
    unsigned long long r;
    asm("mov.b64 %0, {%1, %2};" : "=l"(r) : "f"(x), "f"(y));
    return r;
}
__device__ __forceinline__ void fma2(unsigned long long& a, unsigned long long x, unsigned long long y) {
    asm("fma.rn.f32x2 %0, %1, %2, %0;" : "+l"(a) : "l"(x), "l"(y));
}
__device__ __forceinline__ float2 unpack2(unsigned long long v) {
    float2 r;
    asm("mov.b64 {%0, %1}, %2;" : "=f"(r.x), "=f"(r.y) : "l"(v));
    return r;
}
// ---------- cp.async helpers ----------
__device__ __forceinline__ void cp16(void* smem_dst, const void* gsrc) {
    unsigned sa = (unsigned)__cvta_generic_to_shared(smem_dst);
    asm volatile("cp.async.cg.shared.global [%0], [%1], 16;" :: "r"(sa), "l"(gsrc));
}
__device__ __forceinline__ void cp_commit() { asm volatile("cp.async.commit_group;"); }
template <int Np>
__device__ __forceinline__ void cp_wait() { asm volatile("cp.async.wait_group %0;" :: "n"(Np)); }

// ---------- kernel 1: codebook row norms + prescale ----------
__global__ void scale_codebook_kernel(const float* __restrict__ cb, int K) {
    int row = blockIdx.x * 8 + (threadIdx.x >> 5);
    int lane = threadIdx.x & 31;
    if (row >= K) return;
    const float4* src = (const float4*)(cb + (size_t)row * 256);
    float4 v0 = src[lane * 2];
    float4 v1 = src[lane * 2 + 1];
    float ss = v0.x * v0.x + v0.y * v0.y + v0.z * v0.z + v0.w * v0.w +
               v1.x * v1.x + v1.y * v1.y + v1.z * v1.z + v1.w * v1.w;
#pragma unroll
    for (int off = 16; off; off >>= 1) ss += __shfl_xor_sync(0xffffffffu, ss, off);
    float inv = 1.0f / fmaxf(sqrtf(ss), EPSQ);
    float4* dst = (float4*)(g_cbs + (size_t)row * 256);
    v0.x *= inv; v0.y *= inv; v0.z *= inv; v0.w *= inv;
    v1.x *= inv; v1.y *= inv; v1.z *= inv; v1.w *= inv;
    dst[lane * 2] = v0;
    dst[lane * 2 + 1] = v1;
}

// ---------- kernel 2: fused GEMM + gumbel + argmax + gather ----------
// 64 rows per block, K in chunks of 64, D=256 resident.
// smem stride 260 floats (65 float4): conflict-free LDS.128 phases.
#define STRF 260
#define STR4 65

__device__ __forceinline__ void load_B_chunk(float* Bsbuf, int kbase, int tid) {
#pragma unroll
    for (int t = 0; t < 16; t++) {
        int fid = tid + t * 256;
        int c = fid >> 6, d4 = fid & 63;
        cp16(Bsbuf + c * STRF + d4 * 4, g_cbs + ((size_t)(kbase + c)) * 256 + d4 * 4);
    }
}

__global__ void __launch_bounds__(256, 1)
quant_main_kernel(const float* __restrict__ latent, const float* __restrict__ noise,
                  const float* __restrict__ cb, const float* __restrict__ tptr,
                  float* __restrict__ out, int N, int K) {
    extern __shared__ float sm[];
    float* As = sm;                 // 64 x 260
    float* Bs = sm + 64 * STRF;     // 2 x 64 x 260
    __shared__ float s_scale[64];
    __shared__ int s_bestk[64];
    __shared__ float s_part[256];

    int tid = threadIdx.x;
    int tx = tid & 15, ty = tid >> 4;
    int rowbase = blockIdx.x * 64;

    // Issue latent tile loads (group 0)
#pragma unroll
    for (int t = 0; t < 16; t++) {
        int fid = tid + t * 256;
        int r = fid >> 6, d4 = fid & 63;
        cp16(As + r * STRF + d4 * 4, latent + ((size_t)(rowbase + r)) * 256 + d4 * 4);
    }
    cp_commit();
    // Issue B chunk 0 (group 1)
    load_B_chunk(Bs, 0, tid);
    cp_commit();

    cp_wait<1>();  // latent tile ready (chunk 0 may still be in flight)
    __syncthreads();

    // Row norms -> per-row scale 1/(max(||l||,eps)*temp)
    {
        int r = tid >> 2, seg = tid & 3;
        const float4* A4 = (const float4*)As;
        float ss = 0.0f;
#pragma unroll
        for (int q = 0; q < 16; q++) {
            float4 v = A4[r * STR4 + seg * 16 + q];
            ss += v.x * v.x + v.y * v.y + v.z * v.z + v.w * v.w;
        }
        s_part[tid] = ss;
    }
    __syncthreads();
    if (tid < 64) {
        float ss = s_part[tid * 4] + s_part[tid * 4 + 1] + s_part[tid * 4 + 2] + s_part[tid * 4 + 3];
        float tv = *tptr;
        s_scale[tid] = 1.0f / (fmaxf(sqrtf(ss), EPSQ) * tv);
    }
    __syncthreads();

    float sr[4];
#pragma unroll
    for (int i = 0; i < 4; i++) sr[i] = s_scale[ty + 16 * i];

    float bestv[4];
    int bestk[4];
#pragma unroll
    for (int i = 0; i < 4; i++) { bestv[i] = -__int_as_float(0x7f800000); bestk[i] = 0; }

    int nchunks = K >> 6;
    for (int c = 0; c < nchunks; c++) {
        int kbase = c << 6;
        if (c + 1 < nchunks) {
            load_B_chunk(Bs + ((c + 1) & 1) * 64 * STRF, kbase + 64, tid);
            cp_commit();
        }
        // Prefetch gumbel for this chunk (overlaps with cp.async wait)
        float g[4][4];
#pragma unroll
        for (int i = 0; i < 4; i++) {
#pragma unroll
            for (int j = 0; j < 4; j++) {
                float u = noise[(size_t)(rowbase + ty + 16 * i) * K + kbase + tx + 16 * j];
                g[i][j] = -logf(-logf(u));  // accurate logf: must track reference f32 chain
            }
        }
        if (c + 1 < nchunks) cp_wait<1>(); else cp_wait<0>();
        __syncthreads();

        const float4* A4 = (const float4*)As;
        const float4* B4 = (const float4*)(Bs + (c & 1) * 64 * STRF);
        const float4* ap[4];
        const float4* bp[4];
#pragma unroll
        for (int i = 0; i < 4; i++) ap[i] = A4 + (ty + 16 * i) * STR4;
#pragma unroll
        for (int j = 0; j < 4; j++) bp[j] = B4 + (tx + 16 * j) * STR4;

        unsigned long long acc[4][4][2];
#pragma unroll
        for (int i = 0; i < 4; i++)
#pragma unroll
            for (int j = 0; j < 4; j++) { acc[i][j][0] = 0ull; acc[i][j][1] = 0ull; }

#pragma unroll 4
        for (int d4 = 0; d4 < 64; ++d4) {
            unsigned long long al[4], ah[4], bl[4], bh[4];
#pragma unroll
            for (int i = 0; i < 4; i++) {
                float4 v = ap[i][d4];
                al[i] = pack2(v.x, v.y);
                ah[i] = pack2(v.z, v.w);
            }
#pragma unroll
            for (int j = 0; j < 4; j++) {
                float4 v = bp[j][d4];
                bl[j] = pack2(v.x, v.y);
                bh[j] = pack2(v.z, v.w);
            }
#pragma unroll
            for (int i = 0; i < 4; i++)
#pragma unroll
                for (int j = 0; j < 4; j++) {
                    fma2(acc[i][j][0], al[i], bl[j]);
                    fma2(acc[i][j][1], ah[i], bh[j]);
                }
        }

        // Epilogue: logits + running argmax (strict > keeps first max index)
#pragma unroll
        for (int i = 0; i < 4; i++) {
#pragma unroll
            for (int j = 0; j < 4; j++) {
                float2 p = unpack2(acc[i][j][0]);
                float2 q = unpack2(acc[i][j][1]);
                float dot = (p.x + p.y) + (q.x + q.y);
                float lg = dot * sr[i] + g[i][j];
                int kk = kbase + tx + 16 * j;
                if (lg > bestv[i]) { bestv[i] = lg; bestk[i] = kk; }
            }
        }
        __syncthreads();  // protect far B buffer before next-next refill
    }

    // Cross-thread argmax per row (16 lanes of a half-warp share a row)
#pragma unroll
    for (int i = 0; i < 4; i++) {
        float v = bestv[i];
        int k = bestk[i];
#pragma unroll
        for (int off = 8; off >= 1; off >>= 1) {
            float ov = __shfl_xor_sync(0xffffffffu, v, off);
            int ok = __shfl_xor_sync(0xffffffffu, k, off);
            if (ov > v || (ov == v && ok < k)) { v = ov; k = ok; }
        }
        if (tx == 0) s_bestk[ty + 16 * i] = k;
    }
    __syncthreads();

    // Gather winning codebook rows (original, unscaled codebook)
    const float4* cb4 = (const float4*)cb;
    float4* out4 = (float4*)out;
#pragma unroll
    for (int t = 0; t < 16; t++) {
        int fid = tid + t * 256;
        int r = fid >> 6, d4 = fid & 63;
        out4[((size_t)(rowbase + r)) * 64 + d4] = cb4[((size_t)s_bestk[r]) * 64 + d4];
    }
}

extern "C" void kernel_launch(void* const* d_in, const int* in_sizes, int n_in,
                              void* d_out, int out_size) {
    const float* latent = (const float*)d_in[0];
    const float* noise  = (const float*)d_in[1];
    const float* cb     = (const float*)d_in[2];
    const float* tptr   = (const float*)d_in[3];

    double s0 = (double)in_sizes[0], s1 = (double)in_sizes[1], s2 = (double)in_sizes[2];
    int D = (int)llround(sqrt(s0 * s2 / s1));   // 256
    int K = in_sizes[2] / D;                    // 1024
    int N = in_sizes[0] / D;                    // 131072

    scale_codebook_kernel<<<(K + 7) / 8, 256>>>(cb, K);

    size_t shmem = (size_t)(64 * STRF + 2 * 64 * STRF) * sizeof(float);  // ~195 KB
    cudaFuncSetAttribute(quant_main_kernel, cudaFuncAttributeMaxDynamicSharedMemorySize, (int)shmem);
    quant_main_kernel<<<N / 64, 256, shmem>>>(latent, noise, cb, tptr, (float*)d_out, N, K);
}